// round 5
// baseline (speedup 1.0000x reference)
#include <cuda_runtime.h>
#include <cstddef>

#define B 32
#define T 2048
#define E 128
#define NC 32            // chunks for x-pass kernels (k1, k3, k7)
#define RPC (T / NC)     // 64 rows per chunk
#define NT 16            // logit tiles for k5 (128 t's each)
#define TPT (T / NT)     // 128
#define INV_T (1.0f / 2048.0f)

// ---------------- scratch (device globals; no allocation allowed) ----------
__device__ float  g_s_part[2][B][NC][E];   // partial column sums of x1 / x2
__device__ float  g_c_part[2][B][NC][E];   // partial c1 / c2 (unscaled)
__device__ float  g_d[2][B][T];            // d1 = x1.W1, d2 = x2.W2
__device__ float  g_et[2][B][T];           // raw logits
__device__ float2 g_stats[2][B][NT];       // per-tile (max, sumexp(local max))
__device__ float  g_o_part[2][B][NC][E];   // partial weighted sums
__device__ unsigned int g_ticket[B];       // zero-init; atomicInc wraps -> 0 each run

static __device__ __forceinline__ float dot4(float4 a, float4 b) {
    return fmaf(a.x, b.x, fmaf(a.y, b.y, fmaf(a.z, b.z, a.w * b.w)));
}

// L2 evict_last access policy (created once per thread, reused for all loads)
static __device__ __forceinline__ unsigned long long mkpol() {
    unsigned long long pol;
    asm("createpolicy.fractional.L2::evict_last.b64 %0, 1.0;" : "=l"(pol));
    return pol;
}

// x loads: non-coherent + L2 evict_last hint so the 64MB of x1+x2 stays
// resident in the 126MB L2 across all three passes and across graph replays.
static __device__ __forceinline__ float4 ldx(const float4* p, unsigned long long pol) {
    float4 v;
    asm("ld.global.nc.L2::cache_hint.v4.f32 {%0,%1,%2,%3}, [%4], %5;"
        : "=f"(v.x), "=f"(v.y), "=f"(v.z), "=f"(v.w) : "l"(p), "l"(pol));
    return v;
}

// ===========================================================================
// K1: column-sum partials s1/s2 AND per-row dots d1 = x1.W1, d2 = x2.W2
// grid (NC, B), block 256 = 8 warps; warp w owns RPC/8 = 8 contiguous rows
// ===========================================================================
__global__ void __launch_bounds__(256) k1_sd(
    const float* __restrict__ x1, const float* __restrict__ x2,
    const float* __restrict__ W1, const float* __restrict__ W2)
{
    int chunk = blockIdx.x, b = blockIdx.y;
    int lane = threadIdx.x & 31, w = threadIdx.x >> 5;
    unsigned long long pol = mkpol();

    float4 w1l = ((const float4*)W1)[lane];
    float4 w2l = ((const float4*)W2)[lane];

    int t0 = chunk * RPC + w * (RPC / 8);
    const float4* p1 = (const float4*)(x1 + ((size_t)b * T + t0) * E) + lane;
    const float4* p2 = (const float4*)(x2 + ((size_t)b * T + t0) * E) + lane;

    float4 s1a = {0,0,0,0}, s2a = {0,0,0,0};
    #pragma unroll 4
    for (int rr = 0; rr < RPC / 8; rr++) {
        float4 v1 = ldx(p1 + rr * (E/4), pol);
        float4 v2 = ldx(p2 + rr * (E/4), pol);
        s1a.x += v1.x; s1a.y += v1.y; s1a.z += v1.z; s1a.w += v1.w;
        s2a.x += v2.x; s2a.y += v2.y; s2a.z += v2.z; s2a.w += v2.w;
        float d1 = dot4(v1, w1l);
        float d2 = dot4(v2, w2l);
        #pragma unroll
        for (int off = 16; off; off >>= 1) {
            d1 += __shfl_xor_sync(0xffffffffu, d1, off);
            d2 += __shfl_xor_sync(0xffffffffu, d2, off);
        }
        if (lane == 0) {
            g_d[0][b][t0 + rr] = d1;
            g_d[1][b][t0 + rr] = d2;
        }
    }

    __shared__ float4 sh1[8][32], sh2[8][32];
    sh1[w][lane] = s1a;
    sh2[w][lane] = s2a;
    __syncthreads();
    if (threadIdx.x < 32) {
        float4 s = sh1[0][lane];
        #pragma unroll
        for (int g = 1; g < 8; g++) {
            float4 v = sh1[g][lane];
            s.x += v.x; s.y += v.y; s.z += v.z; s.w += v.w;
        }
        ((float4*)&g_s_part[0][b][chunk][0])[lane] = s;
    } else if (threadIdx.x < 64) {
        float4 s = sh2[0][lane];
        #pragma unroll
        for (int g = 1; g < 8; g++) {
            float4 v = sh2[g][lane];
            s.x += v.x; s.y += v.y; s.z += v.z; s.w += v.w;
        }
        ((float4*)&g_s_part[1][b][chunk][0])[lane] = s;
    }
}

// ===========================================================================
// K3: a1 = x1[t].s2, a2 = x2[t].s1; accumulate c1 += a1*x2[t], c2 += a2*x1[t]
// grid (NC, B), block 256 = 8 warps, RPC/8 = 8 rows per warp
// ===========================================================================
__global__ void __launch_bounds__(256) k3_c(
    const float* __restrict__ x1, const float* __restrict__ x2)
{
    int chunk = blockIdx.x, b = blockIdx.y;
    int lane = threadIdx.x & 31, w = threadIdx.x >> 5;
    unsigned long long pol = mkpol();

    __shared__ float s_sh[2][E];
    if (threadIdx.x < 128) {
        int e = threadIdx.x;
        float acc = 0.f;
        #pragma unroll
        for (int ch = 0; ch < NC; ch++) acc += g_s_part[0][b][ch][e];
        s_sh[0][e] = acc;
    } else {
        int e = threadIdx.x - 128;
        float acc = 0.f;
        #pragma unroll
        for (int ch = 0; ch < NC; ch++) acc += g_s_part[1][b][ch][e];
        s_sh[1][e] = acc;
    }
    __syncthreads();

    float4 s1l = ((const float4*)s_sh[0])[lane];
    float4 s2l = ((const float4*)s_sh[1])[lane];

    int t0 = chunk * RPC + w * (RPC / 8);
    const float4* p1 = (const float4*)(x1 + ((size_t)b * T + t0) * E) + lane;
    const float4* p2 = (const float4*)(x2 + ((size_t)b * T + t0) * E) + lane;

    float4 c1a = {0,0,0,0}, c2a = {0,0,0,0};
    #pragma unroll 2
    for (int rr = 0; rr < RPC / 8; rr++) {
        float4 v1 = ldx(p1 + rr * (E/4), pol);
        float4 v2 = ldx(p2 + rr * (E/4), pol);
        float a1 = dot4(v1, s2l);   // x1 . s2
        float a2 = dot4(v2, s1l);   // x2 . s1
        #pragma unroll
        for (int off = 16; off; off >>= 1) {
            a1 += __shfl_xor_sync(0xffffffffu, a1, off);
            a2 += __shfl_xor_sync(0xffffffffu, a2, off);
        }
        c1a.x = fmaf(a1, v2.x, c1a.x); c1a.y = fmaf(a1, v2.y, c1a.y);
        c1a.z = fmaf(a1, v2.z, c1a.z); c1a.w = fmaf(a1, v2.w, c1a.w);
        c2a.x = fmaf(a2, v1.x, c2a.x); c2a.y = fmaf(a2, v1.y, c2a.y);
        c2a.z = fmaf(a2, v1.z, c2a.z); c2a.w = fmaf(a2, v1.w, c2a.w);
    }

    __shared__ float4 shc[2][8][32];
    shc[0][w][lane] = c1a;
    shc[1][w][lane] = c2a;
    __syncthreads();
    if (threadIdx.x < 32) {
        float4 s = shc[0][0][lane];
        #pragma unroll
        for (int g = 1; g < 8; g++) {
            float4 v = shc[0][g][lane];
            s.x += v.x; s.y += v.y; s.z += v.z; s.w += v.w;
        }
        ((float4*)&g_c_part[0][b][chunk][0])[lane] = s;
    } else if (threadIdx.x < 64) {
        float4 s = shc[1][0][lane];
        #pragma unroll
        for (int g = 1; g < 8; g++) {
            float4 v = shc[1][g][lane];
            s.x += v.x; s.y += v.y; s.z += v.z; s.w += v.w;
        }
        ((float4*)&g_c_part[1][b][chunk][0])[lane] = s;
    }
}

// ===========================================================================
// K5: et[ti][b][t] = c[ti][b].U[:,t] + d[ti][b][t] + bias[t]
//     + per-tile softmax stats (max, sumexp) per (ti,b,tile)
// grid (NT, 4, 2), block 256: warp per batch (8 batches/block), lane -> 4 t's
// ===========================================================================
__global__ void __launch_bounds__(256) k5_et(
    const float* __restrict__ U1, const float* __restrict__ U2,
    const float* __restrict__ b1, const float* __restrict__ b2)
{
    int tb = blockIdx.x;          // tile 0..15
    int bg = blockIdx.y;          // 0..3
    int ti = blockIdx.z;          // 0..1
    const float* U = ti ? U2 : U1;
    const float* bias = ti ? b2 : b1;
    int b0 = bg * 8, t0 = tb * TPT;

    __shared__ float csh[8][E];
    for (int idx = threadIdx.x; idx < 8 * E; idx += 256) {
        int bi = idx >> 7, e = idx & 127;
        float acc = 0.f;
        #pragma unroll
        for (int ch = 0; ch < NC; ch++) acc += g_c_part[ti][b0 + bi][ch][e];
        csh[bi][e] = acc * INV_T;
    }
    __syncthreads();

    int bi = threadIdx.x >> 5, lane = threadIdx.x & 31;
    const float4* U4 = (const float4*)(U + t0) + lane;
    float4 acc = {0,0,0,0};
    #pragma unroll 8
    for (int e = 0; e < E; e++) {
        float c = csh[bi][e];
        float4 u = U4[e * (T/4)];
        acc.x = fmaf(c, u.x, acc.x);
        acc.y = fmaf(c, u.y, acc.y);
        acc.z = fmaf(c, u.z, acc.z);
        acc.w = fmaf(c, u.w, acc.w);
    }
    int t = t0 + lane * 4;
    float4 dd = *(const float4*)&g_d[ti][b0 + bi][t];
    float4 bb = *(const float4*)(bias + t);
    acc.x += dd.x + bb.x;
    acc.y += dd.y + bb.y;
    acc.z += dd.z + bb.z;
    acc.w += dd.w + bb.w;
    *(float4*)&g_et[ti][b0 + bi][t] = acc;

    // warp-level tile softmax stats (one warp covers the whole 128-t tile)
    float m = fmaxf(fmaxf(acc.x, acc.y), fmaxf(acc.z, acc.w));
    #pragma unroll
    for (int off = 16; off; off >>= 1)
        m = fmaxf(m, __shfl_xor_sync(0xffffffffu, m, off));
    float z = __expf(acc.x - m) + __expf(acc.y - m)
            + __expf(acc.z - m) + __expf(acc.w - m);
    #pragma unroll
    for (int off = 16; off; off >>= 1)
        z += __shfl_xor_sync(0xffffffffu, z, off);
    if (lane == 0)
        g_stats[ti][b0 + bi][tb] = make_float2(m, z);
}

// ===========================================================================
// K7: combine tile stats -> softmax weights (smem) -> weighted-sum partials;
//     last block per batch (ticket) reduces partials and writes the output.
// grid (NC, B), block 256
// ===========================================================================
__global__ void __launch_bounds__(256) k7_o(
    const float* __restrict__ x1, const float* __restrict__ x2,
    float* __restrict__ out)
{
    int chunk = blockIdx.x, b = blockIdx.y;
    int lane = threadIdx.x & 31, grp = threadIdx.x >> 5;
    int t0 = chunk * RPC;
    unsigned long long pol = mkpol();

    // 1) combine the NT tile stats (2 threads only)
    __shared__ float s_m[2], s_iz[2];
    if (threadIdx.x < 2) {
        int ti = threadIdx.x;
        float m = -3.4e38f;
        #pragma unroll
        for (int i = 0; i < NT; i++) m = fmaxf(m, g_stats[ti][b][i].x);
        float z = 0.f;
        #pragma unroll
        for (int i = 0; i < NT; i++) {
            float2 st = g_stats[ti][b][i];
            z += st.y * __expf(st.x - m);
        }
        s_m[ti] = m;
        s_iz[ti] = 1.0f / z;
    }
    __syncthreads();

    // 2) materialize softmax weights for this chunk (first 2*RPC threads)
    __shared__ float wsh[2][RPC];
    if (threadIdx.x < 2 * RPC) {
        int ti = threadIdx.x / RPC, rr = threadIdx.x % RPC;
        wsh[ti][rr] = __expf(g_et[ti][b][t0 + rr] - s_m[ti]) * s_iz[ti];
    }
    __syncthreads();

    // 3) weighted accumulation over the chunk
    const float4* p1 = (const float4*)(x1 + ((size_t)b * T + t0) * E) + lane;
    const float4* p2 = (const float4*)(x2 + ((size_t)b * T + t0) * E) + lane;
    float4 a1 = {0,0,0,0}, a2 = {0,0,0,0};
    #pragma unroll 4
    for (int r = grp; r < RPC; r += 8) {
        float w1 = wsh[0][r];
        float w2 = wsh[1][r];
        float4 v1 = ldx(p1 + r * (E/4), pol);
        float4 v2 = ldx(p2 + r * (E/4), pol);
        a1.x = fmaf(w1, v1.x, a1.x); a1.y = fmaf(w1, v1.y, a1.y);
        a1.z = fmaf(w1, v1.z, a1.z); a1.w = fmaf(w1, v1.w, a1.w);
        a2.x = fmaf(w2, v2.x, a2.x); a2.y = fmaf(w2, v2.y, a2.y);
        a2.z = fmaf(w2, v2.z, a2.z); a2.w = fmaf(w2, v2.w, a2.w);
    }

    __shared__ float4 sh1[8][32], sh2[8][32];
    sh1[grp][lane] = a1;
    sh2[grp][lane] = a2;
    __syncthreads();
    if (threadIdx.x < 32) {
        float4 s = sh1[0][lane];
        #pragma unroll
        for (int g = 1; g < 8; g++) {
            float4 v = sh1[g][lane];
            s.x += v.x; s.y += v.y; s.z += v.z; s.w += v.w;
        }
        ((float4*)&g_o_part[0][b][chunk][0])[lane] = s;
    } else if (threadIdx.x < 64) {
        float4 s = sh2[0][lane];
        #pragma unroll
        for (int g = 1; g < 8; g++) {
            float4 v = sh2[g][lane];
            s.x += v.x; s.y += v.y; s.z += v.z; s.w += v.w;
        }
        ((float4*)&g_o_part[1][b][chunk][0])[lane] = s;
    }
    __syncthreads();

    // 4) deterministic last-block final reduction (self-resetting ticket)
    __shared__ int s_last;
    if (threadIdx.x == 0) {
        __threadfence();
        unsigned old = atomicInc(&g_ticket[b], NC - 1);
        s_last = (old == NC - 1);
    }
    __syncthreads();
    if (s_last) {
        __threadfence();
        int ti = threadIdx.x >> 7, e = threadIdx.x & 127;
        float acc = 0.f;
        #pragma unroll
        for (int ch = 0; ch < NC; ch++) acc += g_o_part[ti][b][ch][e];
        out[b * 256 + ti * 128 + e] = acc;
    }
}

// ===========================================================================
extern "C" void kernel_launch(void* const* d_in, const int* in_sizes, int n_in,
                              void* d_out, int out_size)
{
    const float* x1 = (const float*)d_in[0];
    const float* x2 = (const float*)d_in[1];
    const float* W1 = (const float*)d_in[2];
    const float* b1 = (const float*)d_in[3];
    const float* U1 = (const float*)d_in[4];
    const float* W2 = (const float*)d_in[5];
    const float* b2 = (const float*)d_in[6];
    const float* U2 = (const float*)d_in[7];
    float* out = (float*)d_out;

    k1_sd<<<dim3(NC, B), 256>>>(x1, x2, W1, W2);
    k3_c<<<dim3(NC, B), 256>>>(x1, x2);
    k5_et<<<dim3(NT, 4, 2), 256>>>(U1, U2, b1, b2);
    k7_o<<<dim3(NC, B), 256>>>(x1, x2, out);
}

// round 6
// speedup vs baseline: 1.3707x; 1.3707x over previous
#include <cuda_runtime.h>
#include <cstddef>

#define B_   32
#define T_   2048
#define E_   128
#define G_   4              // CTAs per batch
#define ROWS 512            // T_ / G_  rows per CTA
#define NW   16             // warps per CTA
#define RPW  32             // rows per warp
#define INV_T (1.0f / 2048.0f)

// ---------------- scratch (device globals; zero-init; no allocation) -------
__device__ float  g_s_part[2][B_][G_][E_];   // per-CTA column-sum partials
__device__ float  g_c_part[2][B_][G_][E_];   // per-CTA c partials
__device__ float2 g_stats [2][B_][G_];       // per-CTA (max, sumexp) stats
__device__ float  g_o_part[2][B_][G_][E_];   // per-CTA weighted-sum partials
__device__ unsigned g_bar[B_][5];            // per-batch phase counters (self-reset)

static __device__ __forceinline__ float dot4(float4 a, float4 b) {
    return fmaf(a.x, b.x, fmaf(a.y, b.y, fmaf(a.z, b.z, a.w * b.w)));
}
static __device__ __forceinline__ float wsum(float v) {
    #pragma unroll
    for (int off = 16; off; off >>= 1) v += __shfl_xor_sync(0xffffffffu, v, off);
    return v;
}
static __device__ __forceinline__ float wmax(float v) {
    #pragma unroll
    for (int off = 16; off; off >>= 1) v = fmaxf(v, __shfl_xor_sync(0xffffffffu, v, off));
    return v;
}

// batch-scoped barrier: all G_ CTAs of this batch arrive, then proceed.
// All 128 CTAs are co-resident (grid 128 <= 148 SMs), so spinning is safe.
static __device__ __forceinline__ void batch_bar(unsigned* cnt) {
    __threadfence();                 // make this thread's global writes visible
    __syncthreads();
    if (threadIdx.x == 0) {
        atomicAdd(cnt, 1u);
        while (*(volatile unsigned*)cnt < G_) __nanosleep(32);
        __threadfence();
    }
    __syncthreads();
}

// ===========================================================================
__global__ void __launch_bounds__(512, 1) fused_attn(
    const float* __restrict__ x1, const float* __restrict__ x2,
    const float* __restrict__ W1, const float* __restrict__ bb1,
    const float* __restrict__ U1, const float* __restrict__ W2,
    const float* __restrict__ bb2, const float* __restrict__ U2,
    float* __restrict__ out)
{
    const int b    = blockIdx.x >> 2;
    const int g    = blockIdx.x & 3;
    const int tid  = threadIdx.x;
    const int lane = tid & 31;
    const int w    = tid >> 5;
    const int t0   = g * ROWS;
    const int rbase = w * RPW;

    __shared__ float4 sred[2][NW][32];   // warp-reduction scratch (16 KB)
    __shared__ float  vsh[2][E_];        // s (phase B) then c (phase C)
    __shared__ float  tsh[2][ROWS];      // d -> et -> softmax weights
    __shared__ float2 stsh[2][NW];       // per-warp softmax stats
    __shared__ float  s_m[2], s_iz[2];

    const float4* p1 = (const float4*)(x1 + ((size_t)b * T_ + t0) * E_);
    const float4* p2 = (const float4*)(x2 + ((size_t)b * T_ + t0) * E_);

    // ---------------- Phase A: column-sum partials + row dots d ------------
    {
        float4 w1l = ((const float4*)W1)[lane];
        float4 w2l = ((const float4*)W2)[lane];
        float4 s1a = {0,0,0,0}, s2a = {0,0,0,0};
        #pragma unroll 4
        for (int rr = 0; rr < RPW; rr++) {
            int row = rbase + rr;
            float4 v1 = __ldg(p1 + row * 32 + lane);
            float4 v2 = __ldg(p2 + row * 32 + lane);
            s1a.x += v1.x; s1a.y += v1.y; s1a.z += v1.z; s1a.w += v1.w;
            s2a.x += v2.x; s2a.y += v2.y; s2a.z += v2.z; s2a.w += v2.w;
            float d1 = wsum(dot4(v1, w1l));
            float d2 = wsum(dot4(v2, w2l));
            if (lane == 0) { tsh[0][row] = d1; tsh[1][row] = d2; }
        }
        sred[0][w][lane] = s1a;
        sred[1][w][lane] = s2a;
        __syncthreads();
        if (tid < 64) {
            int ti = tid >> 5;
            float4 s = sred[ti][0][lane];
            #pragma unroll
            for (int k = 1; k < NW; k++) {
                float4 v = sred[ti][k][lane];
                s.x += v.x; s.y += v.y; s.z += v.z; s.w += v.w;
            }
            ((float4*)&g_s_part[ti][b][g][0])[lane] = s;
        }
    }
    batch_bar(&g_bar[b][0]);

    // full column sums into smem
    if (tid < 256) {
        int ti = tid >> 7, e = tid & 127;
        float acc = 0.f;
        #pragma unroll
        for (int gg = 0; gg < G_; gg++) acc += g_s_part[ti][b][gg][e];
        vsh[ti][e] = acc;
    }
    __syncthreads();

    // ---------------- Phase B: c partials (x rows now L2-hot) --------------
    {
        float4 s1l = ((const float4*)vsh[0])[lane];
        float4 s2l = ((const float4*)vsh[1])[lane];
        float4 c1a = {0,0,0,0}, c2a = {0,0,0,0};
        #pragma unroll 4
        for (int rr = 0; rr < RPW; rr++) {
            int row = rbase + rr;
            float4 v1 = __ldg(p1 + row * 32 + lane);
            float4 v2 = __ldg(p2 + row * 32 + lane);
            float a1 = wsum(dot4(v1, s2l));   // x1 . s2
            float a2 = wsum(dot4(v2, s1l));   // x2 . s1
            c1a.x = fmaf(a1, v2.x, c1a.x); c1a.y = fmaf(a1, v2.y, c1a.y);
            c1a.z = fmaf(a1, v2.z, c1a.z); c1a.w = fmaf(a1, v2.w, c1a.w);
            c2a.x = fmaf(a2, v1.x, c2a.x); c2a.y = fmaf(a2, v1.y, c2a.y);
            c2a.z = fmaf(a2, v1.z, c2a.z); c2a.w = fmaf(a2, v1.w, c2a.w);
        }
        sred[0][w][lane] = c1a;
        sred[1][w][lane] = c2a;
        __syncthreads();
        if (tid < 64) {
            int ti = tid >> 5;
            float4 s = sred[ti][0][lane];
            #pragma unroll
            for (int k = 1; k < NW; k++) {
                float4 v = sred[ti][k][lane];
                s.x += v.x; s.y += v.y; s.z += v.z; s.w += v.w;
            }
            ((float4*)&g_c_part[ti][b][g][0])[lane] = s;
        }
    }
    batch_bar(&g_bar[b][1]);

    // full c (scaled) into smem
    if (tid < 256) {
        int ti = tid >> 7, e = tid & 127;
        float acc = 0.f;
        #pragma unroll
        for (int gg = 0; gg < G_; gg++) acc += g_c_part[ti][b][gg][e];
        vsh[ti][e] = acc * INV_T;
    }
    __syncthreads();

    // ---------------- Phase C: logits + per-CTA softmax stats --------------
    {
        #pragma unroll
        for (int p = 0; p < 2; p++) {
            const float* U    = p ? U2  : U1;
            const float* bias = p ? bb2 : bb1;
            int tloc = w * 32 + lane;       // 16 warps x 32 lanes = 512 t's
            int t    = t0 + tloc;
            float acc = 0.f;
            #pragma unroll 8
            for (int e = 0; e < E_; e++)
                acc = fmaf(vsh[p][e], __ldg(&U[e * T_ + t]), acc);
            float et = acc + tsh[p][tloc] + __ldg(&bias[t]);
            tsh[p][tloc] = et;              // overwrite d with logit
            float m = wmax(et);
            float z = wsum(__expf(et - m));
            if (lane == 0) stsh[p][w] = make_float2(m, z);
        }
    }
    __syncthreads();
    if (tid < 2) {
        float m = -3.4e38f;
        #pragma unroll
        for (int i = 0; i < NW; i++) m = fmaxf(m, stsh[tid][i].x);
        float z = 0.f;
        #pragma unroll
        for (int i = 0; i < NW; i++) {
            float2 st = stsh[tid][i];
            z += st.y * __expf(st.x - m);
        }
        g_stats[tid][b][g] = make_float2(m, z);
    }
    batch_bar(&g_bar[b][2]);
    if (tid < 2) {
        float m = -3.4e38f;
        #pragma unroll
        for (int gg = 0; gg < G_; gg++) m = fmaxf(m, g_stats[tid][b][gg].x);
        float z = 0.f;
        #pragma unroll
        for (int gg = 0; gg < G_; gg++) {
            float2 st = g_stats[tid][b][gg];
            z += st.y * __expf(st.x - m);
        }
        s_m[tid]  = m;
        s_iz[tid] = 1.0f / z;
    }
    __syncthreads();

    // ---------------- Phase D: softmax weights + weighted sums -------------
    #pragma unroll
    for (int idx = tid; idx < 2 * ROWS; idx += 512) {
        int ti = idx >> 9, rr = idx & (ROWS - 1);
        tsh[ti][rr] = __expf(tsh[ti][rr] - s_m[ti]) * s_iz[ti];
    }
    __syncthreads();
    {
        float4 o1a = {0,0,0,0}, o2a = {0,0,0,0};
        #pragma unroll 4
        for (int rr = 0; rr < RPW; rr++) {
            int row = rbase + rr;
            float wt1 = tsh[0][row];
            float wt2 = tsh[1][row];
            float4 v1 = __ldg(p1 + row * 32 + lane);
            float4 v2 = __ldg(p2 + row * 32 + lane);
            o1a.x = fmaf(wt1, v1.x, o1a.x); o1a.y = fmaf(wt1, v1.y, o1a.y);
            o1a.z = fmaf(wt1, v1.z, o1a.z); o1a.w = fmaf(wt1, v1.w, o1a.w);
            o2a.x = fmaf(wt2, v2.x, o2a.x); o2a.y = fmaf(wt2, v2.y, o2a.y);
            o2a.z = fmaf(wt2, v2.z, o2a.z); o2a.w = fmaf(wt2, v2.w, o2a.w);
        }
        sred[0][w][lane] = o1a;
        sred[1][w][lane] = o2a;
        __syncthreads();
        if (tid < 64) {
            int ti = tid >> 5;
            float4 s = sred[ti][0][lane];
            #pragma unroll
            for (int k = 1; k < NW; k++) {
                float4 v = sred[ti][k][lane];
                s.x += v.x; s.y += v.y; s.z += v.z; s.w += v.w;
            }
            ((float4*)&g_o_part[ti][b][g][0])[lane] = s;
        }
    }
    batch_bar(&g_bar[b][3]);

    // ---------------- output: CTA g writes its 64 of 256 values ------------
    if (tid < 64) {
        int idx = g * 64 + tid;            // 0..255 across the 4 CTAs
        int ti = idx >> 7, e = idx & 127;
        float acc = 0.f;
        #pragma unroll
        for (int gg = 0; gg < G_; gg++) acc += g_o_part[ti][b][gg][e];
        out[b * 256 + idx] = acc;
    }

    // ---------------- cleanup: last CTA of the batch resets counters -------
    __syncthreads();
    if (tid == 0) {
        unsigned old = atomicAdd(&g_bar[b][4], 1u);
        if (old == G_ - 1) {
            #pragma unroll
            for (int i = 0; i < 5; i++) g_bar[b][i] = 0u;
        }
    }
}

// ===========================================================================
extern "C" void kernel_launch(void* const* d_in, const int* in_sizes, int n_in,
                              void* d_out, int out_size)
{
    const float* x1 = (const float*)d_in[0];
    const float* x2 = (const float*)d_in[1];
    const float* W1 = (const float*)d_in[2];
    const float* b1 = (const float*)d_in[3];
    const float* U1 = (const float*)d_in[4];
    const float* W2 = (const float*)d_in[5];
    const float* b2 = (const float*)d_in[6];
    const float* U2 = (const float*)d_in[7];
    float* out = (float*)d_out;

    fused_attn<<<B_ * G_, 512>>>(x1, x2, W1, b1, U1, W2, b2, U2, out);
}

// round 8
// speedup vs baseline: 1.4555x; 1.0618x over previous
#include <cuda_runtime.h>
#include <cstddef>

#define B_   32
#define T_   2048
#define E_   128
#define G_   4              // CTAs per batch
#define ROWS 512            // T_ / G_  rows per CTA
#define NW   32             // warps per CTA
#define RPW  16             // rows per warp
#define INV_T (1.0f / 2048.0f)

// ---------------- scratch (device globals; zero-init; no allocation) -------
__device__ float  g_s_part[2][B_][G_][E_];   // per-CTA column-sum partials
__device__ float  g_c_part[2][B_][G_][E_];   // per-CTA c partials
__device__ float2 g_stats [2][B_][G_];       // per-CTA (max, sumexp) stats
__device__ float  g_o_part[2][B_][G_][E_];   // per-CTA weighted-sum partials
__device__ unsigned g_bar[B_][5];            // per-batch phase counters (self-reset)

static __device__ __forceinline__ float dot4(float4 a, float4 b) {
    return fmaf(a.x, b.x, fmaf(a.y, b.y, fmaf(a.z, b.z, a.w * b.w)));
}
static __device__ __forceinline__ float wsum(float v) {
    #pragma unroll
    for (int off = 16; off; off >>= 1) v += __shfl_xor_sync(0xffffffffu, v, off);
    return v;
}
static __device__ __forceinline__ float wmax(float v) {
    #pragma unroll
    for (int off = 16; off; off >>= 1) v = fmaxf(v, __shfl_xor_sync(0xffffffffu, v, off));
    return v;
}

// batch-scoped barrier: all G_ CTAs of this batch arrive, then proceed.
// All 128 CTAs are co-resident (grid 128 <= 148 SMs, 1 CTA/SM), so spinning is safe.
static __device__ __forceinline__ void batch_bar(unsigned* cnt) {
    __threadfence();
    __syncthreads();
    if (threadIdx.x == 0) {
        atomicAdd(cnt, 1u);
        while (*(volatile unsigned*)cnt < G_) __nanosleep(32);
        __threadfence();
    }
    __syncthreads();
}

// ===========================================================================
__global__ void __launch_bounds__(1024, 1) fused_attn(
    const float* __restrict__ x1, const float* __restrict__ x2,
    const float* __restrict__ W1, const float* __restrict__ bb1,
    const float* __restrict__ U1, const float* __restrict__ W2,
    const float* __restrict__ bb2, const float* __restrict__ U2,
    float* __restrict__ out)
{
    const int b    = blockIdx.x >> 2;
    const int g    = blockIdx.x & 3;
    const int tid  = threadIdx.x;
    const int lane = tid & 31;
    const int w    = tid >> 5;
    const int t0   = g * ROWS;
    const int rbase = w * RPW;

    __shared__ float4 sred[2][NW][32];   // warp-reduction scratch (32 KB)
    __shared__ float  vsh[2][E_];        // s (phase B) then c (phase C)
    __shared__ float  tsh[2][ROWS];      // d -> et -> softmax weights
    __shared__ float2 stsh[2][16];       // per-warp softmax stats (16 warps/tensor)
    __shared__ float  s_m[2], s_iz[2];

    const float4* p1 = (const float4*)(x1 + ((size_t)b * T_ + t0) * E_);
    const float4* p2 = (const float4*)(x2 + ((size_t)b * T_ + t0) * E_);

    // ---------------- Phase A: column-sum partials + row dots d ------------
    {
        float4 w1l = ((const float4*)W1)[lane];
        float4 w2l = ((const float4*)W2)[lane];
        float4 s1a = {0,0,0,0}, s2a = {0,0,0,0};
        #pragma unroll 2
        for (int rr = 0; rr < RPW; rr++) {
            int row = rbase + rr;
            float4 v1 = __ldg(p1 + row * 32 + lane);
            float4 v2 = __ldg(p2 + row * 32 + lane);
            s1a.x += v1.x; s1a.y += v1.y; s1a.z += v1.z; s1a.w += v1.w;
            s2a.x += v2.x; s2a.y += v2.y; s2a.z += v2.z; s2a.w += v2.w;
            float d1 = wsum(dot4(v1, w1l));
            float d2 = wsum(dot4(v2, w2l));
            if (lane == 0) { tsh[0][row] = d1; tsh[1][row] = d2; }
        }
        sred[0][w][lane] = s1a;
        sred[1][w][lane] = s2a;
        __syncthreads();
        if (tid < 64) {
            int ti = tid >> 5;
            float4 s = sred[ti][0][lane];
            #pragma unroll
            for (int k = 1; k < NW; k++) {
                float4 v = sred[ti][k][lane];
                s.x += v.x; s.y += v.y; s.z += v.z; s.w += v.w;
            }
            ((float4*)&g_s_part[ti][b][g][0])[lane] = s;
        }
    }
    batch_bar(&g_bar[b][0]);

    // full column sums into smem
    if (tid < 256) {
        int ti = tid >> 7, e = tid & 127;
        float acc = 0.f;
        #pragma unroll
        for (int gg = 0; gg < G_; gg++) acc += g_s_part[ti][b][gg][e];
        vsh[ti][e] = acc;
    }
    __syncthreads();

    // ---------------- Phase B: c partials (x rows now L2-hot) --------------
    {
        float4 s1l = ((const float4*)vsh[0])[lane];
        float4 s2l = ((const float4*)vsh[1])[lane];
        float4 c1a = {0,0,0,0}, c2a = {0,0,0,0};
        #pragma unroll 2
        for (int rr = 0; rr < RPW; rr++) {
            int row = rbase + rr;
            float4 v1 = __ldg(p1 + row * 32 + lane);
            float4 v2 = __ldg(p2 + row * 32 + lane);
            float a1 = wsum(dot4(v1, s2l));   // x1 . s2
            float a2 = wsum(dot4(v2, s1l));   // x2 . s1
            c1a.x = fmaf(a1, v2.x, c1a.x); c1a.y = fmaf(a1, v2.y, c1a.y);
            c1a.z = fmaf(a1, v2.z, c1a.z); c1a.w = fmaf(a1, v2.w, c1a.w);
            c2a.x = fmaf(a2, v1.x, c2a.x); c2a.y = fmaf(a2, v1.y, c2a.y);
            c2a.z = fmaf(a2, v1.z, c2a.z); c2a.w = fmaf(a2, v1.w, c2a.w);
        }
        sred[0][w][lane] = c1a;
        sred[1][w][lane] = c2a;
        __syncthreads();
        if (tid < 64) {
            int ti = tid >> 5;
            float4 s = sred[ti][0][lane];
            #pragma unroll
            for (int k = 1; k < NW; k++) {
                float4 v = sred[ti][k][lane];
                s.x += v.x; s.y += v.y; s.z += v.z; s.w += v.w;
            }
            ((float4*)&g_c_part[ti][b][g][0])[lane] = s;
        }
    }
    batch_bar(&g_bar[b][1]);

    // full c (scaled) into smem
    if (tid < 256) {
        int ti = tid >> 7, e = tid & 127;
        float acc = 0.f;
        #pragma unroll
        for (int gg = 0; gg < G_; gg++) acc += g_c_part[ti][b][gg][e];
        vsh[ti][e] = acc * INV_T;
    }
    __syncthreads();

    // ---------------- Phase C: logits + per-CTA softmax stats --------------
    {
        // tensor p = tid/512; one thread per logit (512 t's per tensor)
        int p    = tid >> 9;
        int tloc = tid & 511;
        int wp   = tloc >> 5;              // warp index within tensor (0..15)
        const float* U    = p ? U2  : U1;
        const float* bias = p ? bb2 : bb1;
        int t = t0 + tloc;
        float acc = 0.f;
        #pragma unroll 8
        for (int e = 0; e < E_; e++)
            acc = fmaf(vsh[p][e], __ldg(&U[e * T_ + t]), acc);
        float et = acc + tsh[p][tloc] + __ldg(&bias[t]);
        __syncthreads();                   // tsh read (d) before overwrite
        tsh[p][tloc] = et;
        float m = wmax(et);
        float z = wsum(__expf(et - m));
        if (lane == 0) stsh[p][wp] = make_float2(m, z);
    }
    __syncthreads();
    if (tid < 2) {
        float m = -3.4e38f;
        #pragma unroll
        for (int i = 0; i < 16; i++) m = fmaxf(m, stsh[tid][i].x);
        float z = 0.f;
        #pragma unroll
        for (int i = 0; i < 16; i++) {
            float2 st = stsh[tid][i];
            z += st.y * __expf(st.x - m);
        }
        g_stats[tid][b][g] = make_float2(m, z);
    }
    batch_bar(&g_bar[b][2]);
    if (tid < 2) {
        float m = -3.4e38f;
        #pragma unroll
        for (int gg = 0; gg < G_; gg++) m = fmaxf(m, g_stats[tid][b][gg].x);
        float z = 0.f;
        #pragma unroll
        for (int gg = 0; gg < G_; gg++) {
            float2 st = g_stats[tid][b][gg];
            z += st.y * __expf(st.x - m);
        }
        s_m[tid]  = m;
        s_iz[tid] = 1.0f / z;
    }
    __syncthreads();

    // ---------------- Phase D: softmax weights + weighted sums -------------
    {
        int ti = tid >> 9, rr = tid & 511;     // 1024 threads = 2*ROWS exactly
        tsh[ti][rr] = __expf(tsh[ti][rr] - s_m[ti]) * s_iz[ti];
    }
    __syncthreads();
    {
        float4 o1a = {0,0,0,0}, o2a = {0,0,0,0};
        #pragma unroll 2
        for (int rr = 0; rr < RPW; rr++) {
            int row = rbase + rr;
            float wt1 = tsh[0][row];
            float wt2 = tsh[1][row];
            float4 v1 = __ldg(p1 + row * 32 + lane);
            float4 v2 = __ldg(p2 + row * 32 + lane);
            o1a.x = fmaf(wt1, v1.x, o1a.x); o1a.y = fmaf(wt1, v1.y, o1a.y);
            o1a.z = fmaf(wt1, v1.z, o1a.z); o1a.w = fmaf(wt1, v1.w, o1a.w);
            o2a.x = fmaf(wt2, v2.x, o2a.x); o2a.y = fmaf(wt2, v2.y, o2a.y);
            o2a.z = fmaf(wt2, v2.z, o2a.z); o2a.w = fmaf(wt2, v2.w, o2a.w);
        }
        sred[0][w][lane] = o1a;
        sred[1][w][lane] = o2a;
        __syncthreads();
        if (tid < 64) {
            int ti = tid >> 5;
            float4 s = sred[ti][0][lane];
            #pragma unroll
            for (int k = 1; k < NW; k++) {
                float4 v = sred[ti][k][lane];
                s.x += v.x; s.y += v.y; s.z += v.z; s.w += v.w;
            }
            ((float4*)&g_o_part[ti][b][g][0])[lane] = s;
        }
    }
    batch_bar(&g_bar[b][3]);

    // ---------------- output: CTA g writes its 64 of 256 values ------------
    if (tid < 64) {
        int idx = g * 64 + tid;
        int ti = idx >> 7, e = idx & 127;
        float acc = 0.f;
        #pragma unroll
        for (int gg = 0; gg < G_; gg++) acc += g_o_part[ti][b][gg][e];
        out[b * 256 + idx] = acc;
    }

    // ---------------- cleanup: last CTA of the batch resets counters -------
    __syncthreads();
    if (tid == 0) {
        unsigned old = atomicAdd(&g_bar[b][4], 1u);
        if (old == G_ - 1) {
            #pragma unroll
            for (int i = 0; i < 5; i++) g_bar[b][i] = 0u;
        }
    }
}

// ===========================================================================
extern "C" void kernel_launch(void* const* d_in, const int* in_sizes, int n_in,
                              void* d_out, int out_size)
{
    const float* x1 = (const float*)d_in[0];
    const float* x2 = (const float*)d_in[1];
    const float* W1 = (const float*)d_in[2];
    const float* b1 = (const float*)d_in[3];
    const float* U1 = (const float*)d_in[4];
    const float* W2 = (const float*)d_in[5];
    const float* b2 = (const float*)d_in[6];
    const float* U2 = (const float*)d_in[7];
    float* out = (float*)d_out;

    fused_attn<<<B_ * G_, 1024>>>(x1, x2, W1, b1, U1, W2, b2, U2, out);
}